// round 9
// baseline (speedup 1.0000x reference)
#include <cuda_runtime.h>
#include <cuda_bf16.h>
#include <math.h>

// ---------------- problem constants ----------------
#define NBATCH 1024      // N*M
#define TSTEPS 300
#define HID    128
#define GATES  512       // 4*HID
#define FEAT   45        // V*C
#define NCLS   60
#define NROWS  (TSTEPS*NBATCH)   // 307200 GEMM rows

// ---------------- scratch (device globals; no allocation allowed) ----------
__device__ float g_gates[(size_t)NROWS * GATES];     // 629 MB, layer-0 gate inputs
__device__ float g_hlast[NBATCH * HID];
__device__ float g_weffT[FEAT * GATES];              // [f][g] fused cheb+wih0
__device__ float g_beff0[GATES];
__device__ float g_beff1[GATES];
// per-gate weight planes: [gate][k*HID + j]
__device__ float g_w0p[4][HID * HID];                // whh0
__device__ float g_w1p[4][HID * HID];                // whh1
__device__ float g_wip[4][HID * HID];                // wih1

// skeleton edges
__constant__ int c_src[28] = {0,2,4,1,3,5,6,8,10,7,9,11,13,12,2,4,14,3,5,14,8,10,13,9,11,13,12,13};
__constant__ int c_dst[28] = {2,4,14,3,5,14,8,10,13,9,11,13,14,13,0,2,4,1,3,5,6,8,10,7,9,11,13,14};

// ---------------- precompute: L_hat, fused cheb weights, weight repacks ----
__global__ __launch_bounds__(512) void precompute_kernel(
    const float* __restrict__ w0, const float* __restrict__ w1, const float* __restrict__ chb,
    const float* __restrict__ wih0, const float* __restrict__ whh0,
    const float* __restrict__ bih0, const float* __restrict__ bhh0,
    const float* __restrict__ wih1, const float* __restrict__ whh1,
    const float* __restrict__ bih1, const float* __restrict__ bhh1)
{
    __shared__ float L[15][15];
    int tid = threadIdx.x;
    if (tid < 225) L[tid / 15][tid % 15] = 0.0f;
    __syncthreads();
    if (tid == 0) {
        for (int e = 0; e < 28; e++) L[c_dst[e]][c_src[e]] = 1.0f;
        float dinv[15];
        for (int v = 0; v < 15; v++) {
            float d = 0.f;
            for (int jj = 0; jj < 15; jj++) d += L[v][jj];
            dinv[v] = (d > 0.f) ? rsqrtf(d) : 0.f;
        }
        for (int v = 0; v < 15; v++)
            for (int jj = 0; jj < 15; jj++)
                L[v][jj] = -(dinv[v] * L[v][jj] * dinv[jj]);
    }
    __syncthreads();

    // fused cheb -> W_eff, b_eff   (thread = gate row g)
    {
        int g = tid; // 0..511
        float be = bih0[g] + bhh0[g];
        for (int v = 0; v < 15; v++)
            for (int co = 0; co < 3; co++)
                be += wih0[g * FEAT + v * 3 + co] * chb[co];
        g_beff0[g] = be;
        g_beff1[g] = bih1[g] + bhh1[g];

        for (int f = 0; f < FEAT; f++) {
            int v = f / 3, c = f - v * 3;
            float s = 0.f;
            for (int co = 0; co < 3; co++)
                s += wih0[g * FEAT + v * 3 + co] * w0[co * 3 + c];
            for (int jj = 0; jj < 15; jj++) {
                float lv = L[jj][v];
                if (lv != 0.f) {
                    for (int co = 0; co < 3; co++)
                        s += wih0[g * FEAT + jj * 3 + co] * lv * w1[co * 3 + c];
                }
            }
            g_weffT[f * GATES + g] = s;
        }
    }

    // per-gate plane repack: plane[g][k*HID + j] = W[(g*HID + j)*HID + k]
    for (int idx = tid; idx < HID * HID; idx += 512) {
        int k = idx >> 7, j = idx & 127;
#pragma unroll
        for (int g = 0; g < 4; g++) {
            g_w0p[g][idx] = whh0[((g * HID + j) * HID) + k];
            g_w1p[g][idx] = whh1[((g * HID + j) * HID) + k];
            g_wip[g][idx] = wih1[((g * HID + j) * HID) + k];
        }
    }
}

// ---------------- G0: gather(x1) @ W_eff^T + b_eff --------------------------
__global__ __launch_bounds__(256) void g0_gemm_kernel(const float* __restrict__ x1)
{
    __shared__ float Xs[64][FEAT + 1];
    __shared__ float Ws[FEAT][128];
    __shared__ float Bs[128];
    int ct = blockIdx.x;            // 0..3
    int r0 = blockIdx.y * 64;
    int tid = threadIdx.x;

    for (int idx = tid; idx < FEAT * 128; idx += 256) {
        int k = idx >> 7, c = idx & 127;
        Ws[k][c] = g_weffT[k * GATES + ct * 128 + c];
    }
    if (tid < 128) Bs[tid] = g_beff0[ct * 128 + tid];
    for (int idx = tid; idx < FEAT * 64; idx += 256) {
        int f = idx >> 6, i = idx & 63;
        int r = r0 + i;
        int t = r >> 10, b = r & 1023;
        int n = b >> 1, m = b & 1;
        int v = f / 3, c = f - v * 3;
        Xs[i][f] = x1[(((size_t)(n * 3 + c) * 300 + t) * 15 + v) * 2 + m];
    }
    __syncthreads();

    int ty = tid >> 4, tx = tid & 15;
    float acc[4][8];
#pragma unroll
    for (int a = 0; a < 4; a++)
#pragma unroll
        for (int b = 0; b < 8; b++) acc[a][b] = 0.f;

#pragma unroll 5
    for (int k = 0; k < FEAT; k++) {
        float xv[4], wv[8];
#pragma unroll
        for (int ii = 0; ii < 4; ii++) xv[ii] = Xs[ty * 4 + ii][k];
#pragma unroll
        for (int jj = 0; jj < 8; jj++) wv[jj] = Ws[k][tx + jj * 16];
#pragma unroll
        for (int ii = 0; ii < 4; ii++)
#pragma unroll
            for (int jj = 0; jj < 8; jj++)
                acc[ii][jj] = fmaf(xv[ii], wv[jj], acc[ii][jj]);
    }
#pragma unroll
    for (int ii = 0; ii < 4; ii++) {
        size_t rowbase = (size_t)(r0 + ty * 4 + ii) * GATES + ct * 128;
#pragma unroll
        for (int jj = 0; jj < 8; jj++) {
            int c = tx + jj * 16;
            g_gates[rowbase + c] = acc[ii][jj] + Bs[c];
        }
    }
}

// ---------------- fused 2-layer LSTM (batch-parallel, gate-split) -----------
// 128 CTAs x 512 threads. CTA owns 8 batch rows.
// Thread = (gate g = tid>>7, hidden j = tid&127): accumulates gate g of hidden
// unit j for all 8 batches, for layer0 (whh0) and layer1 (whh1 + wih1).
// Weights are per-gate planes -> every weight byte fetched ONCE per CTA per
// step (no duplication). h kept in smem as [j][b] so per-k reads are two
// broadcast LDS.128. Gate values exchanged via smem; group g updates batches
// 2g..2g+1 (owns their c-state).
__device__ __forceinline__ float fsigm(float x) { return 1.f / (1.f + __expf(-x)); }
__device__ __forceinline__ float ftanh(float x) {
    return 1.f - 2.f / (__expf(2.f * x) + 1.f);
}

__global__ __launch_bounds__(512) void fused_lstm_kernel()
{
    __shared__ float h0sm[HID][8];
    __shared__ float h1sm[HID][8];
    __shared__ float gx[4][HID][8];   // [gate][j][batch] exchange
    int tid = threadIdx.x;
    int g   = tid >> 7;               // gate 0..3 (uniform per warp)
    int j   = tid & 127;
    int b0  = blockIdx.x * 8;

    const float* __restrict__ wa0 = g_w0p[g];
    const float* __restrict__ wa1 = g_w1p[g];
    const float* __restrict__ wc  = g_wip[g];
    float bias1 = g_beff1[g * HID + j];

    for (int idx = tid; idx < HID * 8; idx += 512) {
        ((float*)h0sm)[idx] = 0.f;
        ((float*)h1sm)[idx] = 0.f;
    }
    float cs0[2] = {0.f, 0.f};        // c-state for batches 2g, 2g+1
    float cs1[2] = {0.f, 0.f};
    __syncthreads();

    for (int t = 0; t < TSTEPS; t++) {
        // ---- phase A: both recurrences from old h (gate g only) ----
        float a0[8], a1[8];
#pragma unroll
        for (int b = 0; b < 8; b++) { a0[b] = 0.f; a1[b] = 0.f; }

#pragma unroll 4
        for (int k = 0; k < HID; k++) {
            float w0v = wa0[k * HID + j];
            float w1v = wa1[k * HID + j];
            float4 h0a = *(const float4*)&h0sm[k][0];
            float4 h0b = *(const float4*)&h0sm[k][4];
            float4 h1a = *(const float4*)&h1sm[k][0];
            float4 h1b = *(const float4*)&h1sm[k][4];
            a0[0] = fmaf(w0v, h0a.x, a0[0]);
            a0[1] = fmaf(w0v, h0a.y, a0[1]);
            a0[2] = fmaf(w0v, h0a.z, a0[2]);
            a0[3] = fmaf(w0v, h0a.w, a0[3]);
            a0[4] = fmaf(w0v, h0b.x, a0[4]);
            a0[5] = fmaf(w0v, h0b.y, a0[5]);
            a0[6] = fmaf(w0v, h0b.z, a0[6]);
            a0[7] = fmaf(w0v, h0b.w, a0[7]);
            a1[0] = fmaf(w1v, h1a.x, a1[0]);
            a1[1] = fmaf(w1v, h1a.y, a1[1]);
            a1[2] = fmaf(w1v, h1a.z, a1[2]);
            a1[3] = fmaf(w1v, h1a.w, a1[3]);
            a1[4] = fmaf(w1v, h1b.x, a1[4]);
            a1[5] = fmaf(w1v, h1b.y, a1[5]);
            a1[6] = fmaf(w1v, h1b.z, a1[6]);
            a1[7] = fmaf(w1v, h1b.w, a1[7]);
        }

        // add layer-0 gmem gate inputs, publish layer-0 gate values
        {
            const float* __restrict__ gb =
                g_gates + ((size_t)t * NBATCH + b0) * GATES + g * HID + j;
#pragma unroll
            for (int b = 0; b < 8; b++)
                gx[g][j][b] = a0[b] + gb[(size_t)b * GATES];
        }
        __syncthreads();   // h reads done + gx(layer0) published

        // ---- phase B: layer-0 cell update; group g owns batches 2g,2g+1 ----
        {
            int bb = 2 * g;
#pragma unroll
            for (int u = 0; u < 2; u++) {
                int b = bb + u;
                float gi = gx[0][j][b];
                float gf = gx[1][j][b];
                float gg = gx[2][j][b];
                float go = gx[3][j][b];
                cs0[u] = fsigm(gf) * cs0[u] + fsigm(gi) * ftanh(gg);
                h0sm[j][b] = fsigm(go) * ftanh(cs0[u]);
            }
        }
        __syncthreads();   // h0 updated; gx free for reuse

        // ---- phase C: layer-1 input GEMM from fresh h0 ----
#pragma unroll 4
        for (int k = 0; k < HID; k++) {
            float wv = wc[k * HID + j];
            float4 ha = *(const float4*)&h0sm[k][0];
            float4 hb = *(const float4*)&h0sm[k][4];
            a1[0] = fmaf(wv, ha.x, a1[0]);
            a1[1] = fmaf(wv, ha.y, a1[1]);
            a1[2] = fmaf(wv, ha.z, a1[2]);
            a1[3] = fmaf(wv, ha.w, a1[3]);
            a1[4] = fmaf(wv, hb.x, a1[4]);
            a1[5] = fmaf(wv, hb.y, a1[5]);
            a1[6] = fmaf(wv, hb.z, a1[6]);
            a1[7] = fmaf(wv, hb.w, a1[7]);
        }
#pragma unroll
        for (int b = 0; b < 8; b++)
            gx[g][j][b] = a1[b] + bias1;
        __syncthreads();   // gx(layer1) published

        // ---- layer-1 cell update ----
        {
            int bb = 2 * g;
#pragma unroll
            for (int u = 0; u < 2; u++) {
                int b = bb + u;
                float gi = gx[0][j][b];
                float gf = gx[1][j][b];
                float gg = gx[2][j][b];
                float go = gx[3][j][b];
                cs1[u] = fsigm(gf) * cs1[u] + fsigm(gi) * ftanh(gg);
                float h = fsigm(go) * ftanh(cs1[u]);
                h1sm[j][b] = h;
                if (t == TSTEPS - 1) g_hlast[(b0 + b) * HID + j] = h;
            }
        }
        __syncthreads();   // h1 updated before next step's phase A
    }
}

// ---------------- FC + softmax ---------------------------------------------
__global__ __launch_bounds__(64) void fc_softmax_kernel(
    const float* __restrict__ fcw, const float* __restrict__ fcb, float* __restrict__ out)
{
    int row = blockIdx.x;
    int tid = threadIdx.x;
    __shared__ float hrow[HID];
    __shared__ float red[64];
    hrow[tid]      = g_hlast[row * HID + tid];
    hrow[tid + 64] = g_hlast[row * HID + 64 + tid];
    __syncthreads();

    float logit = 0.f;
    if (tid < NCLS) {
        logit = fcb[tid];
#pragma unroll 8
        for (int k = 0; k < HID; k++)
            logit = fmaf(hrow[k], fcw[tid * HID + k], logit);
    }
    red[tid] = (tid < NCLS) ? logit : -INFINITY;
    __syncthreads();
    for (int s = 32; s > 0; s >>= 1) {
        if (tid < s) red[tid] = fmaxf(red[tid], red[tid + s]);
        __syncthreads();
    }
    float mx = red[0];
    __syncthreads();
    float e = (tid < NCLS) ? expf(logit - mx) : 0.f;
    red[tid] = e;
    __syncthreads();
    for (int s = 32; s > 0; s >>= 1) {
        if (tid < s) red[tid] += red[tid + s];
        __syncthreads();
    }
    float inv = 1.f / red[0];
    if (tid < NCLS) out[row * NCLS + tid] = e * inv;
}

// ---------------- launch ----------------------------------------------------
extern "C" void kernel_launch(void* const* d_in, const int* in_sizes, int n_in,
                              void* d_out, int out_size)
{
    const float* x1   = (const float*)d_in[0];
    const float* w0   = (const float*)d_in[2];
    const float* w1   = (const float*)d_in[3];
    const float* chb  = (const float*)d_in[4];
    const float* wih0 = (const float*)d_in[5];
    const float* whh0 = (const float*)d_in[6];
    const float* bih0 = (const float*)d_in[7];
    const float* bhh0 = (const float*)d_in[8];
    const float* wih1 = (const float*)d_in[9];
    const float* whh1 = (const float*)d_in[10];
    const float* bih1 = (const float*)d_in[11];
    const float* bhh1 = (const float*)d_in[12];
    const float* fcw  = (const float*)d_in[13];
    const float* fcb  = (const float*)d_in[14];
    float* out = (float*)d_out;

    precompute_kernel<<<1, 512>>>(w0, w1, chb, wih0, whh0, bih0, bhh0,
                                  wih1, whh1, bih1, bhh1);
    g0_gemm_kernel<<<dim3(4, NROWS / 64), 256>>>(x1);
    fused_lstm_kernel<<<NBATCH / 8, 512>>>();
    fc_softmax_kernel<<<NBATCH, 64>>>(fcw, fcb, out);
}

// round 11
// speedup vs baseline: 1.4182x; 1.4182x over previous
#include <cuda_runtime.h>
#include <cuda_bf16.h>
#include <math.h>

// ---------------- problem constants ----------------
#define NBATCH 1024      // N*M
#define TSTEPS 300
#define HID    128
#define GATES  512       // 4*HID
#define FEAT   45        // V*C
#define NCLS   60
#define NROWS  (TSTEPS*NBATCH)   // 307200 GEMM rows

// ---------------- scratch (device globals; no allocation allowed) ----------
__device__ float g_gates[(size_t)NROWS * GATES];     // 629 MB, layer-0 gate inputs
__device__ float g_hlast[NBATCH * HID];
__device__ float g_weffT[FEAT * GATES];              // [f][g] fused cheb+wih0
__device__ float g_beff0[GATES];
__device__ float g_beff1[GATES];
// per-gate weight planes: [gate][k*HID + j]
__device__ float g_w0p[4][HID * HID];                // whh0
__device__ float g_w1p[4][HID * HID];                // whh1
__device__ float g_wip[4][HID * HID];                // wih1

// skeleton edges
__constant__ int c_src[28] = {0,2,4,1,3,5,6,8,10,7,9,11,13,12,2,4,14,3,5,14,8,10,13,9,11,13,12,13};
__constant__ int c_dst[28] = {2,4,14,3,5,14,8,10,13,9,11,13,14,13,0,2,4,1,3,5,6,8,10,7,9,11,13,14};

// ---------------- precompute: L_hat, fused cheb weights, weight repacks ----
__global__ __launch_bounds__(512) void precompute_kernel(
    const float* __restrict__ w0, const float* __restrict__ w1, const float* __restrict__ chb,
    const float* __restrict__ wih0, const float* __restrict__ whh0,
    const float* __restrict__ bih0, const float* __restrict__ bhh0,
    const float* __restrict__ wih1, const float* __restrict__ whh1,
    const float* __restrict__ bih1, const float* __restrict__ bhh1)
{
    __shared__ float L[15][15];
    int tid = threadIdx.x;
    if (tid < 225) L[tid / 15][tid % 15] = 0.0f;
    __syncthreads();
    if (tid == 0) {
        for (int e = 0; e < 28; e++) L[c_dst[e]][c_src[e]] = 1.0f;
        float dinv[15];
        for (int v = 0; v < 15; v++) {
            float d = 0.f;
            for (int jj = 0; jj < 15; jj++) d += L[v][jj];
            dinv[v] = (d > 0.f) ? rsqrtf(d) : 0.f;
        }
        for (int v = 0; v < 15; v++)
            for (int jj = 0; jj < 15; jj++)
                L[v][jj] = -(dinv[v] * L[v][jj] * dinv[jj]);
    }
    __syncthreads();

    // fused cheb -> W_eff, b_eff   (thread = gate row g)
    {
        int g = tid; // 0..511
        float be = bih0[g] + bhh0[g];
        for (int v = 0; v < 15; v++)
            for (int co = 0; co < 3; co++)
                be += wih0[g * FEAT + v * 3 + co] * chb[co];
        g_beff0[g] = be;
        g_beff1[g] = bih1[g] + bhh1[g];

        for (int f = 0; f < FEAT; f++) {
            int v = f / 3, c = f - v * 3;
            float s = 0.f;
            for (int co = 0; co < 3; co++)
                s += wih0[g * FEAT + v * 3 + co] * w0[co * 3 + c];
            for (int jj = 0; jj < 15; jj++) {
                float lv = L[jj][v];
                if (lv != 0.f) {
                    for (int co = 0; co < 3; co++)
                        s += wih0[g * FEAT + jj * 3 + co] * lv * w1[co * 3 + c];
                }
            }
            g_weffT[f * GATES + g] = s;
        }
    }

    // per-gate plane repack: plane[g][k*HID + j] = W[(g*HID + j)*HID + k]
    for (int idx = tid; idx < HID * HID; idx += 512) {
        int k = idx >> 7, j = idx & 127;
#pragma unroll
        for (int g = 0; g < 4; g++) {
            g_w0p[g][idx] = whh0[((g * HID + j) * HID) + k];
            g_w1p[g][idx] = whh1[((g * HID + j) * HID) + k];
            g_wip[g][idx] = wih1[((g * HID + j) * HID) + k];
        }
    }
}

// ---------------- G0: gather(x1) @ W_eff^T + b_eff --------------------------
__global__ __launch_bounds__(256) void g0_gemm_kernel(const float* __restrict__ x1)
{
    __shared__ float Xs[64][FEAT + 1];
    __shared__ float Ws[FEAT][128];
    __shared__ float Bs[128];
    int ct = blockIdx.x;            // 0..3
    int r0 = blockIdx.y * 64;
    int tid = threadIdx.x;

    for (int idx = tid; idx < FEAT * 128; idx += 256) {
        int k = idx >> 7, c = idx & 127;
        Ws[k][c] = g_weffT[k * GATES + ct * 128 + c];
    }
    if (tid < 128) Bs[tid] = g_beff0[ct * 128 + tid];
    for (int idx = tid; idx < FEAT * 64; idx += 256) {
        int f = idx >> 6, i = idx & 63;
        int r = r0 + i;
        int t = r >> 10, b = r & 1023;
        int n = b >> 1, m = b & 1;
        int v = f / 3, c = f - v * 3;
        Xs[i][f] = x1[(((size_t)(n * 3 + c) * 300 + t) * 15 + v) * 2 + m];
    }
    __syncthreads();

    int ty = tid >> 4, tx = tid & 15;
    float acc[4][8];
#pragma unroll
    for (int a = 0; a < 4; a++)
#pragma unroll
        for (int b = 0; b < 8; b++) acc[a][b] = 0.f;

#pragma unroll 5
    for (int k = 0; k < FEAT; k++) {
        float xv[4], wv[8];
#pragma unroll
        for (int ii = 0; ii < 4; ii++) xv[ii] = Xs[ty * 4 + ii][k];
#pragma unroll
        for (int jj = 0; jj < 8; jj++) wv[jj] = Ws[k][tx + jj * 16];
#pragma unroll
        for (int ii = 0; ii < 4; ii++)
#pragma unroll
            for (int jj = 0; jj < 8; jj++)
                acc[ii][jj] = fmaf(xv[ii], wv[jj], acc[ii][jj]);
    }
#pragma unroll
    for (int ii = 0; ii < 4; ii++) {
        size_t rowbase = (size_t)(r0 + ty * 4 + ii) * GATES + ct * 128;
#pragma unroll
        for (int jj = 0; jj < 8; jj++) {
            int c = tx + jj * 16;
            g_gates[rowbase + c] = acc[ii][jj] + Bs[c];
        }
    }
}

// ---------------- fused 2-layer LSTM (batch-parallel, gate+k split) ---------
// 128 CTAs x 1024 threads (8 warps/SMSP). CTA owns 8 batch rows.
// Thread = (kh = tid>>9, g = (tid>>7)&3, j = tid&127): accumulates gate g of
// hidden unit j over its 64-element k-half, for all 8 batches, for both
// layers. Weight k-halves are disjoint -> each weight byte still fetched once
// per CTA per step. Partials exchanged in gx[kh][g][b][j] (j innermost:
// every LDS/STS conflict-free). Cell updates: 1024 threads <-> 1024 (j,b)
// cells, one c-state register per thread per layer.
__device__ __forceinline__ float fsigm(float x) { return 1.f / (1.f + __expf(-x)); }
__device__ __forceinline__ float ftanh(float x) {
    return 1.f - 2.f / (__expf(2.f * x) + 1.f);
}

__global__ __launch_bounds__(1024) void fused_lstm_kernel()
{
    __shared__ float h0sm[HID][8];
    __shared__ float h1sm[HID][8];
    __shared__ float gx[2][4][8][HID];   // [khalf][gate][batch][j]
    int tid = threadIdx.x;
    int kh  = tid >> 9;                  // k-half 0/1
    int g   = (tid >> 7) & 3;            // gate
    int j   = tid & 127;                 // hidden index
    int bown = tid >> 7;                 // cell-update batch (0..7)
    int b0  = blockIdx.x * 8;

    const float* __restrict__ wa0 = g_w0p[g] + (kh * 64) * HID + j;
    const float* __restrict__ wa1 = g_w1p[g] + (kh * 64) * HID + j;
    const float* __restrict__ wc  = g_wip[g] + (kh * 64) * HID + j;
    float bias1 = (kh == 0) ? g_beff1[g * HID + j] : 0.f;
    const float* h0k = &h0sm[kh * 64][0];
    const float* h1k = &h1sm[kh * 64][0];

    for (int idx = tid; idx < HID * 8; idx += 1024) {
        ((float*)h0sm)[idx] = 0.f;
        ((float*)h1sm)[idx] = 0.f;
    }
    float cs0 = 0.f, cs1 = 0.f;          // c-state for cell (j, bown)
    __syncthreads();

    for (int t = 0; t < TSTEPS; t++) {
        // ---- phase A: both recurrences from old h (gate g, k-half kh) ----
        float a0[8], a1[8];
#pragma unroll
        for (int b = 0; b < 8; b++) { a0[b] = 0.f; a1[b] = 0.f; }

#pragma unroll 4
        for (int kk = 0; kk < 64; kk++) {
            float w0v = wa0[kk * HID];
            float w1v = wa1[kk * HID];
            float4 h0a = *(const float4*)(h0k + kk * 8);
            float4 h0b = *(const float4*)(h0k + kk * 8 + 4);
            float4 h1a = *(const float4*)(h1k + kk * 8);
            float4 h1b = *(const float4*)(h1k + kk * 8 + 4);
            a0[0] = fmaf(w0v, h0a.x, a0[0]);
            a0[1] = fmaf(w0v, h0a.y, a0[1]);
            a0[2] = fmaf(w0v, h0a.z, a0[2]);
            a0[3] = fmaf(w0v, h0a.w, a0[3]);
            a0[4] = fmaf(w0v, h0b.x, a0[4]);
            a0[5] = fmaf(w0v, h0b.y, a0[5]);
            a0[6] = fmaf(w0v, h0b.z, a0[6]);
            a0[7] = fmaf(w0v, h0b.w, a0[7]);
            a1[0] = fmaf(w1v, h1a.x, a1[0]);
            a1[1] = fmaf(w1v, h1a.y, a1[1]);
            a1[2] = fmaf(w1v, h1a.z, a1[2]);
            a1[3] = fmaf(w1v, h1a.w, a1[3]);
            a1[4] = fmaf(w1v, h1b.x, a1[4]);
            a1[5] = fmaf(w1v, h1b.y, a1[5]);
            a1[6] = fmaf(w1v, h1b.z, a1[6]);
            a1[7] = fmaf(w1v, h1b.w, a1[7]);
        }

        // publish layer-0 partials (kh=0 also adds gmem gate inputs)
        if (kh == 0) {
            const float* __restrict__ gb =
                g_gates + ((size_t)t * NBATCH + b0) * GATES + g * HID + j;
#pragma unroll
            for (int b = 0; b < 8; b++)
                gx[0][g][b][j] = a0[b] + gb[(size_t)b * GATES];
        } else {
#pragma unroll
            for (int b = 0; b < 8; b++)
                gx[1][g][b][j] = a0[b];
        }
        __syncthreads();   // h reads done + layer-0 gx published

        // ---- cell update layer 0: thread owns cell (j, bown) ----
        {
            float gi = gx[0][0][bown][j] + gx[1][0][bown][j];
            float gf = gx[0][1][bown][j] + gx[1][1][bown][j];
            float gg = gx[0][2][bown][j] + gx[1][2][bown][j];
            float go = gx[0][3][bown][j] + gx[1][3][bown][j];
            cs0 = fsigm(gf) * cs0 + fsigm(gi) * ftanh(gg);
            h0sm[j][bown] = fsigm(go) * ftanh(cs0);
        }
        __syncthreads();   // h0 updated; gx reads done

        // ---- phase C: layer-1 input GEMM from fresh h0 (k-half kh) ----
#pragma unroll 4
        for (int kk = 0; kk < 64; kk++) {
            float wv = wc[kk * HID];
            float4 ha = *(const float4*)(h0k + kk * 8);
            float4 hb = *(const float4*)(h0k + kk * 8 + 4);
            a1[0] = fmaf(wv, ha.x, a1[0]);
            a1[1] = fmaf(wv, ha.y, a1[1]);
            a1[2] = fmaf(wv, ha.z, a1[2]);
            a1[3] = fmaf(wv, ha.w, a1[3]);
            a1[4] = fmaf(wv, hb.x, a1[4]);
            a1[5] = fmaf(wv, hb.y, a1[5]);
            a1[6] = fmaf(wv, hb.z, a1[6]);
            a1[7] = fmaf(wv, hb.w, a1[7]);
        }
#pragma unroll
        for (int b = 0; b < 8; b++)
            gx[kh][g][b][j] = a1[b] + bias1;
        __syncthreads();   // layer-1 gx published

        // ---- cell update layer 1 ----
        {
            float gi = gx[0][0][bown][j] + gx[1][0][bown][j];
            float gf = gx[0][1][bown][j] + gx[1][1][bown][j];
            float gg = gx[0][2][bown][j] + gx[1][2][bown][j];
            float go = gx[0][3][bown][j] + gx[1][3][bown][j];
            cs1 = fsigm(gf) * cs1 + fsigm(gi) * ftanh(gg);
            float h = fsigm(go) * ftanh(cs1);
            h1sm[j][bown] = h;
            if (t == TSTEPS - 1) g_hlast[(b0 + bown) * HID + j] = h;
        }
        __syncthreads();   // h1 updated + gx reads done before next step
    }
}

// ---------------- FC + softmax ---------------------------------------------
__global__ __launch_bounds__(64) void fc_softmax_kernel(
    const float* __restrict__ fcw, const float* __restrict__ fcb, float* __restrict__ out)
{
    int row = blockIdx.x;
    int tid = threadIdx.x;
    __shared__ float hrow[HID];
    __shared__ float red[64];
    hrow[tid]      = g_hlast[row * HID + tid];
    hrow[tid + 64] = g_hlast[row * HID + 64 + tid];
    __syncthreads();

    float logit = 0.f;
    if (tid < NCLS) {
        logit = fcb[tid];
#pragma unroll 8
        for (int k = 0; k < HID; k++)
            logit = fmaf(hrow[k], fcw[tid * HID + k], logit);
    }
    red[tid] = (tid < NCLS) ? logit : -INFINITY;
    __syncthreads();
    for (int s = 32; s > 0; s >>= 1) {
        if (tid < s) red[tid] = fmaxf(red[tid], red[tid + s]);
        __syncthreads();
    }
    float mx = red[0];
    __syncthreads();
    float e = (tid < NCLS) ? expf(logit - mx) : 0.f;
    red[tid] = e;
    __syncthreads();
    for (int s = 32; s > 0; s >>= 1) {
        if (tid < s) red[tid] += red[tid + s];
        __syncthreads();
    }
    float inv = 1.f / red[0];
    if (tid < NCLS) out[row * NCLS + tid] = e * inv;
}

// ---------------- launch ----------------------------------------------------
extern "C" void kernel_launch(void* const* d_in, const int* in_sizes, int n_in,
                              void* d_out, int out_size)
{
    const float* x1   = (const float*)d_in[0];
    const float* w0   = (const float*)d_in[2];
    const float* w1   = (const float*)d_in[3];
    const float* chb  = (const float*)d_in[4];
    const float* wih0 = (const float*)d_in[5];
    const float* whh0 = (const float*)d_in[6];
    const float* bih0 = (const float*)d_in[7];
    const float* bhh0 = (const float*)d_in[8];
    const float* wih1 = (const float*)d_in[9];
    const float* whh1 = (const float*)d_in[10];
    const float* bih1 = (const float*)d_in[11];
    const float* bhh1 = (const float*)d_in[12];
    const float* fcw  = (const float*)d_in[13];
    const float* fcb  = (const float*)d_in[14];
    float* out = (float*)d_out;

    precompute_kernel<<<1, 512>>>(w0, w1, chb, wih0, whh0, bih0, bhh0,
                                  wih1, whh1, bih1, bhh1);
    g0_gemm_kernel<<<dim3(4, NROWS / 64), 256>>>(x1);
    fused_lstm_kernel<<<NBATCH / 8, 1024>>>();
    fc_softmax_kernel<<<NBATCH, 64>>>(fcw, fcb, out);
}

// round 13
// speedup vs baseline: 1.4998x; 1.0575x over previous
#include <cuda_runtime.h>
#include <cuda_bf16.h>
#include <math.h>

// ---------------- problem constants ----------------
#define NBATCH 1024      // N*M
#define TSTEPS 300
#define HID    128
#define GATES  512       // 4*HID
#define FEAT   45        // V*C
#define FPAD   48
#define NCLS   60
#define NROWS  (TSTEPS*NBATCH)   // 307200 GEMM rows

// ---------------- scratch (device globals; no allocation allowed) ----------
__device__ float g_gates[(size_t)NROWS * GATES];     // 629 MB, layer-0 gate inputs
__device__ float g_xre[(size_t)NROWS * FPAD];        // 59 MB, transposed input
__device__ float g_hlast[NBATCH * HID];
__device__ float g_weffT[FEAT * GATES];              // [f][g] fused cheb+wih0
__device__ float g_beff0[GATES];
__device__ float g_beff1[GATES];
// per-gate weight planes: [gate][k*HID + j]
__device__ float g_w0p[4][HID * HID];                // whh0
__device__ float g_w1p[4][HID * HID];                // whh1
__device__ float g_wip[4][HID * HID];                // wih1

// skeleton edges
__constant__ int c_src[28] = {0,2,4,1,3,5,6,8,10,7,9,11,13,12,2,4,14,3,5,14,8,10,13,9,11,13,12,13};
__constant__ int c_dst[28] = {2,4,14,3,5,14,8,10,13,9,11,13,14,13,0,2,4,1,3,5,6,8,10,7,9,11,13,14};

// ---------------- input transpose: x1 -> g_xre[r][f] ------------------------
// reads x1 linearly (fully coalesced), writes semi-scattered (55 MB total).
__global__ __launch_bounds__(256) void transpose_kernel(const float* __restrict__ x1)
{
    int lin = blockIdx.x * 256 + threadIdx.x;     // 13.8M elements
    if (lin >= 512 * 3 * 300 * 15 * 2) return;
    float v = x1[lin];
    int m  = lin & 1;
    int vv = (lin >> 1) % 15;
    int t  = (lin / 30) % 300;
    int c  = (lin / 9000) % 3;
    int n  = lin / 27000;
    int r  = t * NBATCH + n * 2 + m;
    int f  = vv * 3 + c;
    g_xre[(size_t)r * FPAD + f] = v;
}

// ---------------- precompute: L_hat, fused cheb weights, weight repacks ----
__global__ __launch_bounds__(512) void precompute_kernel(
    const float* __restrict__ w0, const float* __restrict__ w1, const float* __restrict__ chb,
    const float* __restrict__ wih0, const float* __restrict__ whh0,
    const float* __restrict__ bih0, const float* __restrict__ bhh0,
    const float* __restrict__ wih1, const float* __restrict__ whh1,
    const float* __restrict__ bih1, const float* __restrict__ bhh1)
{
    __shared__ float L[15][15];
    int tid = threadIdx.x;
    if (tid < 225) L[tid / 15][tid % 15] = 0.0f;
    __syncthreads();
    if (tid == 0) {
        for (int e = 0; e < 28; e++) L[c_dst[e]][c_src[e]] = 1.0f;
        float dinv[15];
        for (int v = 0; v < 15; v++) {
            float d = 0.f;
            for (int jj = 0; jj < 15; jj++) d += L[v][jj];
            dinv[v] = (d > 0.f) ? rsqrtf(d) : 0.f;
        }
        for (int v = 0; v < 15; v++)
            for (int jj = 0; jj < 15; jj++)
                L[v][jj] = -(dinv[v] * L[v][jj] * dinv[jj]);
    }
    __syncthreads();

    // fused cheb -> W_eff, b_eff   (thread = gate row g)
    {
        int g = tid; // 0..511
        float be = bih0[g] + bhh0[g];
        for (int v = 0; v < 15; v++)
            for (int co = 0; co < 3; co++)
                be += wih0[g * FEAT + v * 3 + co] * chb[co];
        g_beff0[g] = be;
        g_beff1[g] = bih1[g] + bhh1[g];

        for (int f = 0; f < FEAT; f++) {
            int v = f / 3, c = f - v * 3;
            float s = 0.f;
            for (int co = 0; co < 3; co++)
                s += wih0[g * FEAT + v * 3 + co] * w0[co * 3 + c];
            for (int jj = 0; jj < 15; jj++) {
                float lv = L[jj][v];
                if (lv != 0.f) {
                    for (int co = 0; co < 3; co++)
                        s += wih0[g * FEAT + jj * 3 + co] * lv * w1[co * 3 + c];
                }
            }
            g_weffT[f * GATES + g] = s;
        }
    }

    // per-gate plane repack: plane[g][k*HID + j] = W[(g*HID + j)*HID + k]
    for (int idx = tid; idx < HID * HID; idx += 512) {
        int k = idx >> 7, j = idx & 127;
#pragma unroll
        for (int g = 0; g < 4; g++) {
            g_w0p[g][idx] = whh0[((g * HID + j) * HID) + k];
            g_w1p[g][idx] = whh1[((g * HID + j) * HID) + k];
            g_wip[g][idx] = wih1[((g * HID + j) * HID) + k];
        }
    }
}

// ---------------- G0: g_xre @ W_eff^T + b_eff -------------------------------
__global__ __launch_bounds__(256) void g0_gemm_kernel()
{
    __shared__ float Xs[64][FEAT + 1];
    __shared__ float Ws[FEAT][128];
    __shared__ float Bs[128];
    int ct = blockIdx.x;            // 0..3
    int r0 = blockIdx.y * 64;
    int tid = threadIdx.x;

    for (int idx = tid; idx < FEAT * 128; idx += 256) {
        int k = idx >> 7, c = idx & 127;
        Ws[k][c] = g_weffT[k * GATES + ct * 128 + c];
    }
    if (tid < 128) Bs[tid] = g_beff0[ct * 128 + tid];
    // coalesced tile load from transposed input
    for (int idx = tid; idx < 64 * FPAD; idx += 256) {
        int i = idx / FPAD, f = idx - i * FPAD;
        if (f < FEAT) Xs[i][f] = g_xre[(size_t)(r0 + i) * FPAD + f];
    }
    __syncthreads();

    int ty = tid >> 4, tx = tid & 15;
    float acc[4][8];
#pragma unroll
    for (int a = 0; a < 4; a++)
#pragma unroll
        for (int b = 0; b < 8; b++) acc[a][b] = 0.f;

#pragma unroll 5
    for (int k = 0; k < FEAT; k++) {
        float xv[4], wv[8];
#pragma unroll
        for (int ii = 0; ii < 4; ii++) xv[ii] = Xs[ty * 4 + ii][k];
#pragma unroll
        for (int jj = 0; jj < 8; jj++) wv[jj] = Ws[k][tx + jj * 16];
#pragma unroll
        for (int ii = 0; ii < 4; ii++)
#pragma unroll
            for (int jj = 0; jj < 8; jj++)
                acc[ii][jj] = fmaf(xv[ii], wv[jj], acc[ii][jj]);
    }
#pragma unroll
    for (int ii = 0; ii < 4; ii++) {
        size_t rowbase = (size_t)(r0 + ty * 4 + ii) * GATES + ct * 128;
#pragma unroll
        for (int jj = 0; jj < 8; jj++) {
            int c = tx + jj * 16;
            g_gates[rowbase + c] = acc[ii][jj] + Bs[c];
        }
    }
}

// ---------------- fused 2-layer LSTM (batch-parallel, gate+k split) ---------
// 128 CTAs x 1024 threads (8 warps/SMSP). CTA owns 8 batch rows.
// Thread = (kh, g, j): accumulates gate g of hidden j over its 64-element
// k-half, all 8 batches, both layers. g_gates LDGs hoisted to the top of
// phase A so the 64-iter k-loop hides their latency.
__device__ __forceinline__ float fsigm(float x) { return 1.f / (1.f + __expf(-x)); }
__device__ __forceinline__ float ftanh(float x) {
    return 1.f - 2.f / (__expf(2.f * x) + 1.f);
}

__global__ __launch_bounds__(1024) void fused_lstm_kernel()
{
    __shared__ float h0sm[HID][8];
    __shared__ float h1sm[HID][8];
    __shared__ float gx[2][4][8][HID];   // [khalf][gate][batch][j]
    int tid = threadIdx.x;
    int kh  = tid >> 9;                  // k-half 0/1
    int g   = (tid >> 7) & 3;            // gate
    int j   = tid & 127;                 // hidden index
    int bown = tid >> 7;                 // cell-update batch (0..7)
    int b0  = blockIdx.x * 8;

    const float* __restrict__ wa0 = g_w0p[g] + (kh * 64) * HID + j;
    const float* __restrict__ wa1 = g_w1p[g] + (kh * 64) * HID + j;
    const float* __restrict__ wc  = g_wip[g] + (kh * 64) * HID + j;
    float bias1 = (kh == 0) ? g_beff1[g * HID + j] : 0.f;
    const float* h0k = &h0sm[kh * 64][0];
    const float* h1k = &h1sm[kh * 64][0];

    for (int idx = tid; idx < HID * 8; idx += 1024) {
        ((float*)h0sm)[idx] = 0.f;
        ((float*)h1sm)[idx] = 0.f;
    }
    float cs0 = 0.f, cs1 = 0.f;          // c-state for cell (j, bown)
    __syncthreads();

    for (int t = 0; t < TSTEPS; t++) {
        // ---- hoisted gmem gate-input loads (independent of h) ----
        float gldg[8];
        if (kh == 0) {
            const float* __restrict__ gb =
                g_gates + ((size_t)t * NBATCH + b0) * GATES + g * HID + j;
#pragma unroll
            for (int b = 0; b < 8; b++)
                gldg[b] = gb[(size_t)b * GATES];
        }

        // ---- phase A: both recurrences from old h (gate g, k-half kh) ----
        float a0[8], a1[8];
#pragma unroll
        for (int b = 0; b < 8; b++) { a0[b] = 0.f; a1[b] = 0.f; }

#pragma unroll 4
        for (int kk = 0; kk < 64; kk++) {
            float w0v = wa0[kk * HID];
            float w1v = wa1[kk * HID];
            float4 h0a = *(const float4*)(h0k + kk * 8);
            float4 h0b = *(const float4*)(h0k + kk * 8 + 4);
            float4 h1a = *(const float4*)(h1k + kk * 8);
            float4 h1b = *(const float4*)(h1k + kk * 8 + 4);
            a0[0] = fmaf(w0v, h0a.x, a0[0]);
            a0[1] = fmaf(w0v, h0a.y, a0[1]);
            a0[2] = fmaf(w0v, h0a.z, a0[2]);
            a0[3] = fmaf(w0v, h0a.w, a0[3]);
            a0[4] = fmaf(w0v, h0b.x, a0[4]);
            a0[5] = fmaf(w0v, h0b.y, a0[5]);
            a0[6] = fmaf(w0v, h0b.z, a0[6]);
            a0[7] = fmaf(w0v, h0b.w, a0[7]);
            a1[0] = fmaf(w1v, h1a.x, a1[0]);
            a1[1] = fmaf(w1v, h1a.y, a1[1]);
            a1[2] = fmaf(w1v, h1a.z, a1[2]);
            a1[3] = fmaf(w1v, h1a.w, a1[3]);
            a1[4] = fmaf(w1v, h1b.x, a1[4]);
            a1[5] = fmaf(w1v, h1b.y, a1[5]);
            a1[6] = fmaf(w1v, h1b.z, a1[6]);
            a1[7] = fmaf(w1v, h1b.w, a1[7]);
        }

        // publish layer-0 partials (kh=0 adds the prefetched gate inputs)
        if (kh == 0) {
#pragma unroll
            for (int b = 0; b < 8; b++)
                gx[0][g][b][j] = a0[b] + gldg[b];
        } else {
#pragma unroll
            for (int b = 0; b < 8; b++)
                gx[1][g][b][j] = a0[b];
        }
        __syncthreads();   // h reads done + layer-0 gx published

        // ---- cell update layer 0: thread owns cell (j, bown) ----
        {
            float gi = gx[0][0][bown][j] + gx[1][0][bown][j];
            float gf = gx[0][1][bown][j] + gx[1][1][bown][j];
            float gg = gx[0][2][bown][j] + gx[1][2][bown][j];
            float go = gx[0][3][bown][j] + gx[1][3][bown][j];
            cs0 = fsigm(gf) * cs0 + fsigm(gi) * ftanh(gg);
            h0sm[j][bown] = fsigm(go) * ftanh(cs0);
        }
        __syncthreads();   // h0 updated; gx reads done

        // ---- phase C: layer-1 input GEMM from fresh h0 (k-half kh) ----
#pragma unroll 8
        for (int kk = 0; kk < 64; kk++) {
            float wv = wc[kk * HID];
            float4 ha = *(const float4*)(h0k + kk * 8);
            float4 hb = *(const float4*)(h0k + kk * 8 + 4);
            a1[0] = fmaf(wv, ha.x, a1[0]);
            a1[1] = fmaf(wv, ha.y, a1[1]);
            a1[2] = fmaf(wv, ha.z, a1[2]);
            a1[3] = fmaf(wv, ha.w, a1[3]);
            a1[4] = fmaf(wv, hb.x, a1[4]);
            a1[5] = fmaf(wv, hb.y, a1[5]);
            a1[6] = fmaf(wv, hb.z, a1[6]);
            a1[7] = fmaf(wv, hb.w, a1[7]);
        }
#pragma unroll
        for (int b = 0; b < 8; b++)
            gx[kh][g][b][j] = a1[b] + bias1;
        __syncthreads();   // layer-1 gx published

        // ---- cell update layer 1 ----
        {
            float gi = gx[0][0][bown][j] + gx[1][0][bown][j];
            float gf = gx[0][1][bown][j] + gx[1][1][bown][j];
            float gg = gx[0][2][bown][j] + gx[1][2][bown][j];
            float go = gx[0][3][bown][j] + gx[1][3][bown][j];
            cs1 = fsigm(gf) * cs1 + fsigm(gi) * ftanh(gg);
            float h = fsigm(go) * ftanh(cs1);
            h1sm[j][bown] = h;
            if (t == TSTEPS - 1) g_hlast[(b0 + bown) * HID + j] = h;
        }
        __syncthreads();   // h1 updated + gx reads done before next step
    }
}

// ---------------- FC + softmax ---------------------------------------------
__global__ __launch_bounds__(64) void fc_softmax_kernel(
    const float* __restrict__ fcw, const float* __restrict__ fcb, float* __restrict__ out)
{
    int row = blockIdx.x;
    int tid = threadIdx.x;
    __shared__ float hrow[HID];
    __shared__ float red[64];
    hrow[tid]      = g_hlast[row * HID + tid];
    hrow[tid + 64] = g_hlast[row * HID + 64 + tid];
    __syncthreads();

    float logit = 0.f;
    if (tid < NCLS) {
        logit = fcb[tid];
#pragma unroll 8
        for (int k = 0; k < HID; k++)
            logit = fmaf(hrow[k], fcw[tid * HID + k], logit);
    }
    red[tid] = (tid < NCLS) ? logit : -INFINITY;
    __syncthreads();
    for (int s = 32; s > 0; s >>= 1) {
        if (tid < s) red[tid] = fmaxf(red[tid], red[tid + s]);
        __syncthreads();
    }
    float mx = red[0];
    __syncthreads();
    float e = (tid < NCLS) ? expf(logit - mx) : 0.f;
    red[tid] = e;
    __syncthreads();
    for (int s = 32; s > 0; s >>= 1) {
        if (tid < s) red[tid] += red[tid + s];
        __syncthreads();
    }
    float inv = 1.f / red[0];
    if (tid < NCLS) out[row * NCLS + tid] = e * inv;
}

// ---------------- launch ----------------------------------------------------
extern "C" void kernel_launch(void* const* d_in, const int* in_sizes, int n_in,
                              void* d_out, int out_size)
{
    const float* x1   = (const float*)d_in[0];
    const float* w0   = (const float*)d_in[2];
    const float* w1   = (const float*)d_in[3];
    const float* chb  = (const float*)d_in[4];
    const float* wih0 = (const float*)d_in[5];
    const float* whh0 = (const float*)d_in[6];
    const float* bih0 = (const float*)d_in[7];
    const float* bhh0 = (const float*)d_in[8];
    const float* wih1 = (const float*)d_in[9];
    const float* whh1 = (const float*)d_in[10];
    const float* bih1 = (const float*)d_in[11];
    const float* bhh1 = (const float*)d_in[12];
    const float* fcw  = (const float*)d_in[13];
    const float* fcb  = (const float*)d_in[14];
    float* out = (float*)d_out;

    transpose_kernel<<<(512*3*300*15*2 + 255) / 256, 256>>>(x1);
    precompute_kernel<<<1, 512>>>(w0, w1, chb, wih0, whh0, bih0, bhh0,
                                  wih1, whh1, bih1, bhh1);
    g0_gemm_kernel<<<dim3(4, NROWS / 64), 256>>>();
    fused_lstm_kernel<<<NBATCH / 8, 1024>>>();
    fc_softmax_kernel<<<NBATCH, 64>>>(fcw, fcb, out);
}